// round 3
// baseline (speedup 1.0000x reference)
#include <cuda_runtime.h>
#include <math.h>

#define NSEQ 256
#define TLEN 32
#define MROWS 8192      // NSEQ*TLEN
#define ENCD 200

// scratch (static device allocations are allowed)
__device__ float g_P  [MROWS * 800];
__device__ float g_Ya [MROWS * ENCD];
__device__ float g_Yb [MROWS * ENCD];
__device__ float g_enc[NSEQ * ENCD];
__device__ float g_stk[NSEQ * ENCD];
__device__ float g_WtS[54400];          // repacked streamed Wt rows [240,500)

__device__ __forceinline__ float sigf(float x) { return 1.0f / (1.0f + expf(-x)); }
// accurate tanh via expf (robust even under fast-math)
__device__ __forceinline__ float tanh_acc(float x) {
    float e = expf(-2.0f * fabsf(x));
    float r = (1.0f - e) / (1.0f + e);
    return x >= 0.0f ? r : -r;
}

// ---------------------------------------------------------------------------
// P[m][800] = A[row(m)][0:K] @ W[n][0:K]^T + bias[n]
// ---------------------------------------------------------------------------
__global__ __launch_bounds__(256) void proj_gemm(
    const float* __restrict__ Asrc, const int* __restrict__ tok,
    const float* __restrict__ W, const float* __restrict__ bias,
    float* __restrict__ P, int K)
{
    __shared__ float As[20 * 68];
    __shared__ float Ws[20 * 80];
    __shared__ unsigned long long roff[64];

    const int tid = threadIdx.x;
    const int M0 = blockIdx.x * 64;
    const int N0 = blockIdx.y * 80;

    if (tid < 64) {
        long long o = tok ? (long long)__ldg(&tok[M0 + tid]) * (long long)K
                          : (long long)(M0 + tid) * (long long)K;
        roff[tid] = (unsigned long long)o;
    }
    const int m0 = (tid >> 4) * 4;
    const int n0 = (tid & 15) * 5;

    float acc[4][5];
#pragma unroll
    for (int i = 0; i < 4; i++)
#pragma unroll
        for (int j = 0; j < 5; j++) acc[i][j] = 0.0f;
    __syncthreads();

    for (int kt = 0; kt < K; kt += 20) {
        {
            int i0 = tid * 5;
            int mm = i0 / 20, kk = i0 % 20;
            const float* ap = Asrc + roff[mm] + kt + kk;
#pragma unroll
            for (int q = 0; q < 5; q++) As[(kk + q) * 68 + mm] = ap[q];
        }
        for (int i = tid; i < 1600; i += 256) {
            int nn = i / 20, kk = i % 20;
            Ws[kk * 80 + nn] = __ldg(&W[(size_t)(N0 + nn) * K + kt + kk]);
        }
        __syncthreads();
#pragma unroll
        for (int kk = 0; kk < 20; kk++) {
            float4 a4 = *(const float4*)&As[kk * 68 + m0];
            float a[4] = {a4.x, a4.y, a4.z, a4.w};
            float b[5];
#pragma unroll
            for (int j = 0; j < 5; j++) b[j] = Ws[kk * 80 + n0 + j];
#pragma unroll
            for (int i = 0; i < 4; i++)
#pragma unroll
                for (int j = 0; j < 5; j++) acc[i][j] += a[i] * b[j];
        }
        __syncthreads();
    }
#pragma unroll
    for (int i = 0; i < 4; i++) {
        size_t row = (size_t)(M0 + m0 + i) * 800 + N0 + n0;
#pragma unroll
        for (int j = 0; j < 5; j++)
            P[row + j] = acc[i][j] + __ldg(&bias[N0 + n0 + j]);
    }
}

// ---------------------------------------------------------------------------
// LSTM recurrence (unchanged from round 1)
// ---------------------------------------------------------------------------
__global__ __launch_bounds__(400, 1) void lstm_rec(
    const float* __restrict__ P, const float* __restrict__ Whh2,
    const int* __restrict__ lengths, float* __restrict__ Y)
{
    extern __shared__ float sm[];
    float* sW = sm;
    float* sH = sm + 40000;
    float* sC = sH + 400;
    float* sG = sC + 400;

    const int tid = threadIdx.x;
    const int dir = blockIdx.y;
    const int sq0 = blockIdx.x * 4;

    const float* Wd = Whh2 + dir * 40000;
    for (int i = tid; i < 40000; i += 400) sW[i] = Wd[i];
    for (int i = tid; i < 800; i += 400) sm[40000 + i] = 0.0f;

    const int sPW = tid / 100;
    const int jPW = tid % 100;
    const int myLen = __ldg(&lengths[sq0 + sPW]);
    __syncthreads();

    const float4* sW4 = (const float4*)(sW + tid * 100);
    const float4* sH4 = (const float4*)sH;

    for (int st = 0; st < TLEN; st++) {
        int t = dir ? (TLEN - 1 - st) : st;
        float acc0, acc1, acc2, acc3;
        {
            size_t base = ((size_t)sq0 * TLEN + t) * 800 + dir * 400 + tid;
            acc0 = __ldg(&P[base]);
            acc1 = __ldg(&P[base + 1 * TLEN * 800]);
            acc2 = __ldg(&P[base + 2 * TLEN * 800]);
            acc3 = __ldg(&P[base + 3 * TLEN * 800]);
        }
#pragma unroll
        for (int kq = 0; kq < 25; kq++) {
            float4 w = sW4[kq];
            float4 h0 = sH4[kq], h1 = sH4[25 + kq], h2 = sH4[50 + kq], h3 = sH4[75 + kq];
            acc0 += w.x * h0.x + w.y * h0.y + w.z * h0.z + w.w * h0.w;
            acc1 += w.x * h1.x + w.y * h1.y + w.z * h1.z + w.w * h1.w;
            acc2 += w.x * h2.x + w.y * h2.y + w.z * h2.z + w.w * h2.w;
            acc3 += w.x * h3.x + w.y * h3.y + w.z * h3.z + w.w * h3.w;
        }
        sG[tid] = acc0; sG[400 + tid] = acc1; sG[800 + tid] = acc2; sG[1200 + tid] = acc3;
        __syncthreads();
        {
            float gi = sG[sPW * 400 + jPW];
            float gf = sG[sPW * 400 + 100 + jPW];
            float gg = sG[sPW * 400 + 200 + jPW];
            float go = sG[sPW * 400 + 300 + jPW];
            float c  = sC[sPW * 100 + jPW];
            float cn = sigf(gf) * c + sigf(gi) * tanh_acc(gg);
            float hn = sigf(go) * tanh_acc(cn);
            float outv = 0.0f;
            if (t < myLen) {
                sC[sPW * 100 + jPW] = cn;
                sH[sPW * 100 + jPW] = hn;
                outv = hn;
            }
            Y[((size_t)(sq0 + sPW) * TLEN + t) * ENCD + dir * 100 + jPW] = outv;
        }
        __syncthreads();
    }
}

// ---------------------------------------------------------------------------
__global__ __launch_bounds__(200) void meanpool(
    const float* __restrict__ Y, const int* __restrict__ lengths,
    float* __restrict__ enc)
{
    int s = blockIdx.x, e = threadIdx.x;
    const float* p = Y + (size_t)s * TLEN * ENCD + e;
    float sum = 0.0f;
#pragma unroll
    for (int t = 0; t < TLEN; t++) sum += p[t * ENCD];
    enc[s * ENCD + e] = sum / (float)__ldg(&lengths[s]);
}

// ---------------------------------------------------------------------------
// Repack Wt rows [240,500) so that at GEMV iter q, warp lanes (rr*2+ph) read
// 32 consecutive float4s: dst[((b*25+q)*32 + rr*2+ph)*4 + e]
// ---------------------------------------------------------------------------
__global__ __launch_bounds__(256) void repack_wt(const float* __restrict__ Wt)
{
    int idx = blockIdx.x * 256 + threadIdx.x;     // over 260*200 elements
    if (idx >= 260 * 200) return;
    int rp = idx / 200, k = idx % 200;
    int ph = k / 100, kk = k % 100, q = kk >> 2, e = kk & 3;
    int b = rp >> 4, rr = rp & 15;
    g_WtS[((b * 25 + q) * 32 + rr * 2 + ph) * 4 + e] = Wt[(240 + rp) * 200 + k];
}

// ---------------------------------------------------------------------------
// Parser: ONE CTA, 1024 threads. Top-of-stack cached in smem ring buffers.
// Wt: 240 rows in smem + 260 rows streamed (repacked) from L2 concurrently.
// No cluster barriers, no fences — only __syncthreads.
// ---------------------------------------------------------------------------
#define WT_SMEM_ROWS 240

__global__ __launch_bounds__(1024, 1) void parser_kernel(
    const float* __restrict__ missing, const float* __restrict__ Wa,
    const float* __restrict__ ba, const float* __restrict__ Wt,
    const float* __restrict__ bt, float* __restrict__ out)
{
    extern __shared__ float sm[];
    float* sWt   = sm;                       // 240*200 = 48000
    float* sWa   = sWt + WT_SMEM_ROWS * 200; // 1200
    float* sBt   = sWa + 1200;               // 500
    float* sBuf  = sBt + 500;                // 5 * 200
    float* sPart = sBuf + 1000;              // 1024
    float* sG    = sPart + 1024;             // 500
    float* sMiss = sG + 500;                 // 200
    float* sSc   = sMiss + 200;              // 2

    const int tid = threadIdx.x;

    for (int i = tid; i < WT_SMEM_ROWS * 200; i += 1024) sWt[i] = __ldg(&Wt[i]);
    for (int i = tid; i < 1200; i += 1024) sWa[i] = __ldg(&Wa[i]);
    if (tid < 500) sBt[tid] = __ldg(&bt[tid]);
    if (tid < 200) {
        float mv = __ldg(&missing[tid]);
        sMiss[tid] = mv;
        sBuf[0 * 200 + tid] = mv;            // s1 = missing
        sBuf[1 * 200 + tid] = mv;            // s0 = missing
        sBuf[2 * 200 + tid] = __ldg(&g_enc[tid]);  // b = enc[0]
    }
    const float ba0 = __ldg(&ba[0]), ba1 = __ldg(&ba[1]);

    int i1 = 0, i0 = 1, ib = 2, ipre = 3, isp = 4;
    int sp = 0, bp = 0;
    __syncthreads();

    const int warp = tid >> 5, lane = tid & 31;

    for (int step = 0; step < 2 * NSEQ - 1; step++) {
        // --- speculative prefetch of next s1 candidate (off critical path) ---
        if (tid < 200)
            sBuf[ipre * 200 + tid] = (sp >= 3) ? g_stk[(sp - 3) * ENCD + tid]
                                               : sMiss[tid];
        // --- scores (warps 0,1), replicated decision ---
        if (warp < 2) {
            const float* war = sWa + warp * 600;
            float p = 0.0f;
            for (int k = lane; k < 600; k += 32) {
                float f;
                if (k < 200)      f = sBuf[i1 * 200 + k];
                else if (k < 400) f = sBuf[i0 * 200 + (k - 200)];
                else              f = sBuf[ib * 200 + (k - 400)];
                p += war[k] * f;
            }
#pragma unroll
            for (int o = 16; o > 0; o >>= 1) p += __shfl_down_sync(0xffffffffu, p, o);
            if (lane == 0) sSc[warp] = p + (warp ? ba1 : ba0);
        }
        __syncthreads();

        float m0 = (bp < NSEQ) ? sSc[0] : -1e30f;
        float m1 = (sp >= 2)   ? sSc[1] : -1e30f;
        bool is_shift = (m0 >= m1);          // argmax, first-index tie-break

        if (is_shift) {
            int wp = sp; if (wp > NSEQ - 1) wp = NSEQ - 1;
            if (tid < 200) g_stk[wp * ENCD + tid] = sBuf[ib * 200 + tid];
            int nb = i1; i1 = i0; i0 = ib; ib = nb;
            sp += 1; bp += 1;
            if (tid < 200)
                sBuf[ib * 200 + tid] = (bp < NSEQ) ? __ldg(&g_enc[bp * ENCD + tid])
                                                   : sMiss[tid];
        } else {
            // --- tree-lstm gates: g[500] = Wt @ [h1;h2], 2 threads per row ---
            if (tid < 1000) {
                int r = tid >> 1, ph = tid & 1;
                const float4* xp = (const float4*)(sBuf + (ph ? i0 : i1) * 200);
                float acc = 0.0f;
                if (r < WT_SMEM_ROWS) {
                    const float4* wp4 = (const float4*)(sWt + r * 200 + ph * 100);
#pragma unroll
                    for (int q = 0; q < 25; q++) {
                        float4 w = wp4[q], x = xp[q];
                        acc += w.x * x.x + w.y * x.y + w.z * x.z + w.w * x.w;
                    }
                } else {
                    int sr = r - WT_SMEM_ROWS, b = sr >> 4, rr = sr & 15;
                    const float4* wp4 = (const float4*)g_WtS + (b * 25) * 32 + rr * 2 + ph;
#pragma unroll
                    for (int q = 0; q < 25; q++) {
                        float4 w = __ldg(&wp4[q * 32]);
                        float4 x = xp[q];
                        acc += w.x * x.x + w.y * x.y + w.z * x.z + w.w * x.w;
                    }
                }
                sPart[tid] = acc;
            }
            __syncthreads();
            if (tid < 500) sG[tid] = sPart[2 * tid] + sPart[2 * tid + 1] + sBt[tid];
            __syncthreads();
            if (tid < 100) {
                int j = tid;
                float gi  = sG[j],        gf1 = sG[100 + j], gf2 = sG[200 + j];
                float go  = sG[300 + j],  gu  = sG[400 + j];
                float c1 = sBuf[i1 * 200 + 100 + j];
                float c2 = sBuf[i0 * 200 + 100 + j];
                float c = sigf(gf1) * c1 + sigf(gf2) * c2 + sigf(gi) * tanh_acc(gu);
                float h = sigf(go) * tanh_acc(c);
                sBuf[isp * 200 + j]       = h;
                sBuf[isp * 200 + 100 + j] = c;
                int wp = sp - 2;
                g_stk[wp * ENCD + j]       = h;
                g_stk[wp * ENCD + 100 + j] = c;
            }
            // rotate: (i1,i0,ipre,isp) <- (ipre, isp, i1, i0)
            int n1 = ipre, n0 = isp, np = i1, ns = i0;
            i1 = n1; i0 = n0; ipre = np; isp = ns;
            sp -= 1;
        }
        __syncthreads();
    }
    if (tid < ENCD) out[tid] = g_stk[tid];
}

// ---------------------------------------------------------------------------
extern "C" void kernel_launch(void* const* d_in, const int* in_sizes, int n_in,
                              void* d_out, int out_size)
{
    const int*   tokens  = (const int*)d_in[0];
    const int*   lengths = (const int*)d_in[1];
    const float* emb     = (const float*)d_in[2];
    const float* Wih0    = (const float*)d_in[3];
    const float* Whh0    = (const float*)d_in[4];
    const float* b0      = (const float*)d_in[5];
    const float* Wih12   = (const float*)d_in[6];
    const float* Whh12   = (const float*)d_in[7];
    const float* b12     = (const float*)d_in[8];
    const float* missing = (const float*)d_in[9];
    const float* Wa      = (const float*)d_in[10];
    const float* ba      = (const float*)d_in[11];
    const float* Wt      = (const float*)d_in[12];
    const float* bt      = (const float*)d_in[13];
    float* out = (float*)d_out;

    float *P, *Ya, *Yb, *enc;
    cudaGetSymbolAddress((void**)&P,  g_P);
    cudaGetSymbolAddress((void**)&Ya, g_Ya);
    cudaGetSymbolAddress((void**)&Yb, g_Yb);
    cudaGetSymbolAddress((void**)&enc, g_enc);

    const int lstmSmem = (40000 + 400 + 400 + 1600) * 4;          // 169600
    const int parsSmem = (48000 + 1200 + 500 + 1000 + 1024 + 500 + 200 + 2) * 4; // ~209.7KB
    cudaFuncSetAttribute(lstm_rec, cudaFuncAttributeMaxDynamicSharedMemorySize, lstmSmem);
    cudaFuncSetAttribute(parser_kernel, cudaFuncAttributeMaxDynamicSharedMemorySize, parsSmem);

    dim3 gg(128, 10), rg(64, 2);

    repack_wt<<<204, 256>>>(Wt);
    // layer 0
    proj_gemm<<<gg, 256>>>(emb, tokens, Wih0, b0, P, 300);
    lstm_rec<<<rg, 400, lstmSmem>>>(P, Whh0, lengths, Ya);
    // layer 1
    proj_gemm<<<gg, 256>>>(Ya, nullptr, Wih12, b12, P, 200);
    lstm_rec<<<rg, 400, lstmSmem>>>(P, Whh12, lengths, Yb);
    // layer 2
    proj_gemm<<<gg, 256>>>(Yb, nullptr, Wih12 + 160000, b12 + 800, P, 200);
    lstm_rec<<<rg, 400, lstmSmem>>>(P, Whh12 + 80000, lengths, Ya);
    // pool + parse
    meanpool<<<NSEQ, 200>>>(Ya, lengths, enc);
    parser_kernel<<<1, 1024, parsSmem>>>(missing, Wa, ba, Wt, bt, out);
}

// round 5
// speedup vs baseline: 1.1822x; 1.1822x over previous
#include <cuda_runtime.h>
#include <stdint.h>
#include <math.h>

#define NSEQ 256
#define TLEN 32
#define MROWS 8192      // NSEQ*TLEN
#define ENCD 200

// scratch (static device allocations are allowed)
__device__ float g_P  [MROWS * 800];
__device__ float g_Ya [MROWS * ENCD];
__device__ float g_Yb [MROWS * ENCD];
__device__ float g_enc[NSEQ * ENCD];
__device__ float g_stk[NSEQ * ENCD];

__device__ __forceinline__ float sigf(float x) { return 1.0f / (1.0f + expf(-x)); }
// accurate tanh via expf (robust even under fast-math)
__device__ __forceinline__ float tanh_acc(float x) {
    float e = expf(-2.0f * fabsf(x));
    float r = (1.0f - e) / (1.0f + e);
    return x >= 0.0f ? r : -r;
}
__device__ __forceinline__ float4 ldcg4(const float* p) {
    float4 v;
    asm volatile("ld.global.cg.v4.f32 {%0,%1,%2,%3}, [%4];"
                 : "=f"(v.x), "=f"(v.y), "=f"(v.z), "=f"(v.w) : "l"(p));
    return v;
}
__device__ __forceinline__ void stcg(float* p, float v) {
    asm volatile("st.global.cg.f32 [%0], %1;" :: "l"(p), "f"(v));
}
__device__ __forceinline__ void stcg4(float* p, float4 v) {
    asm volatile("st.global.cg.v4.f32 [%0], {%1,%2,%3,%4};"
                 :: "l"(p), "f"(v.x), "f"(v.y), "f"(v.z), "f"(v.w));
}
__device__ __forceinline__ unsigned int smem_u32(const void* p) {
    unsigned int a;
    asm("{ .reg .u64 t; cvta.to.shared.u64 t, %1; cvt.u32.u64 %0, t; }"
        : "=r"(a) : "l"(p));
    return a;
}
__device__ __forceinline__ unsigned int ctarank() {
    unsigned int r; asm("mov.u32 %0, %%cluster_ctarank;" : "=r"(r)); return r;
}
__device__ __forceinline__ void st_remote_f32(unsigned int laddr, unsigned int peer, float v) {
    asm volatile(
        "{ .reg .b32 ra; mapa.shared::cluster.u32 ra, %0, %1; "
        "st.shared::cluster.f32 [ra], %2; }"
        :: "r"(laddr), "r"(peer), "f"(v) : "memory");
}
__device__ __forceinline__ void mbar_init(unsigned int addr, unsigned int count) {
    asm volatile("mbarrier.init.shared.b64 [%0], %1;" :: "r"(addr), "r"(count) : "memory");
}
__device__ __forceinline__ void mbar_arrive_local(unsigned int addr) {
    asm volatile("mbarrier.arrive.shared.b64 _, [%0];" :: "r"(addr) : "memory");
}
__device__ __forceinline__ void mbar_arrive_remote(unsigned int laddr, unsigned int peer) {
    asm volatile(
        "{ .reg .b32 ra; mapa.shared::cluster.u32 ra, %0, %1; "
        "mbarrier.arrive.shared::cluster.b64 _, [ra]; }"
        :: "r"(laddr), "r"(peer) : "memory");
}
__device__ __forceinline__ void mbar_wait(unsigned int addr, unsigned int parity) {
    asm volatile(
        "{\n\t.reg .pred P1;\n\t"
        "WL%=:\n\t"
        "mbarrier.try_wait.parity.acquire.cta.shared::cta.b64 P1, [%0], %1, 0x989680;\n\t"
        "@P1 bra.uni WD%=;\n\t"
        "bra.uni WL%=;\n\t"
        "WD%=:\n\t}"
        :: "r"(addr), "r"(parity) : "memory");
    asm volatile("fence.acq_rel.cluster;" ::: "memory");
}

// ---------------------------------------------------------------------------
// P[m][800] = A[row(m)][0:K] @ W[n][0:K]^T + bias[n]
// ---------------------------------------------------------------------------
__global__ __launch_bounds__(256) void proj_gemm(
    const float* __restrict__ Asrc, const int* __restrict__ tok,
    const float* __restrict__ W, const float* __restrict__ bias,
    float* __restrict__ P, int K)
{
    __shared__ float As[20 * 68];
    __shared__ float Ws[20 * 80];
    __shared__ unsigned long long roff[64];

    const int tid = threadIdx.x;
    const int M0 = blockIdx.x * 64;
    const int N0 = blockIdx.y * 80;

    if (tid < 64) {
        long long o = tok ? (long long)__ldg(&tok[M0 + tid]) * (long long)K
                          : (long long)(M0 + tid) * (long long)K;
        roff[tid] = (unsigned long long)o;
    }
    const int m0 = (tid >> 4) * 4;
    const int n0 = (tid & 15) * 5;

    float acc[4][5];
#pragma unroll
    for (int i = 0; i < 4; i++)
#pragma unroll
        for (int j = 0; j < 5; j++) acc[i][j] = 0.0f;
    __syncthreads();

    for (int kt = 0; kt < K; kt += 20) {
        {
            int i0 = tid * 5;
            int mm = i0 / 20, kk = i0 % 20;
            const float* ap = Asrc + roff[mm] + kt + kk;
#pragma unroll
            for (int q = 0; q < 5; q++) As[(kk + q) * 68 + mm] = ap[q];
        }
        for (int i = tid; i < 1600; i += 256) {
            int nn = i / 20, kk = i % 20;
            Ws[kk * 80 + nn] = __ldg(&W[(size_t)(N0 + nn) * K + kt + kk]);
        }
        __syncthreads();
#pragma unroll
        for (int kk = 0; kk < 20; kk++) {
            float4 a4 = *(const float4*)&As[kk * 68 + m0];
            float a[4] = {a4.x, a4.y, a4.z, a4.w};
            float b[5];
#pragma unroll
            for (int j = 0; j < 5; j++) b[j] = Ws[kk * 80 + n0 + j];
#pragma unroll
            for (int i = 0; i < 4; i++)
#pragma unroll
                for (int j = 0; j < 5; j++) acc[i][j] += a[i] * b[j];
        }
        __syncthreads();
    }
#pragma unroll
    for (int i = 0; i < 4; i++) {
        size_t row = (size_t)(M0 + m0 + i) * 800 + N0 + n0;
#pragma unroll
        for (int j = 0; j < 5; j++)
            P[row + j] = acc[i][j] + __ldg(&bias[N0 + n0 + j]);
    }
}

// ---------------------------------------------------------------------------
// LSTM recurrence with software-pipelined P loads
// ---------------------------------------------------------------------------
__global__ __launch_bounds__(400, 1) void lstm_rec(
    const float* __restrict__ P, const float* __restrict__ Whh2,
    const int* __restrict__ lengths, float* __restrict__ Y)
{
    extern __shared__ float sm[];
    float* sW = sm;
    float* sH = sm + 40000;
    float* sC = sH + 400;
    float* sG = sC + 400;

    const int tid = threadIdx.x;
    const int dir = blockIdx.y;
    const int sq0 = blockIdx.x * 4;

    const float* Wd = Whh2 + dir * 40000;
    for (int i = tid; i < 40000; i += 400) sW[i] = Wd[i];
    for (int i = tid; i < 800; i += 400) sm[40000 + i] = 0.0f;

    const int sPW = tid / 100;
    const int jPW = tid % 100;
    const int myLen = __ldg(&lengths[sq0 + sPW]);
    __syncthreads();

    const float4* sW4 = (const float4*)(sW + tid * 100);
    const float4* sH4 = (const float4*)sH;

    // preload P for first timestep
    float p0, p1, p2, p3;
    {
        int t = dir ? (TLEN - 1) : 0;
        size_t base = ((size_t)sq0 * TLEN + t) * 800 + dir * 400 + tid;
        p0 = __ldg(&P[base]);
        p1 = __ldg(&P[base + 1 * TLEN * 800]);
        p2 = __ldg(&P[base + 2 * TLEN * 800]);
        p3 = __ldg(&P[base + 3 * TLEN * 800]);
    }

    for (int st = 0; st < TLEN; st++) {
        int t = dir ? (TLEN - 1 - st) : st;
        float acc0 = p0, acc1 = p1, acc2 = p2, acc3 = p3;
        if (st + 1 < TLEN) {
            int tn = dir ? (TLEN - 2 - st) : (st + 1);
            size_t base = ((size_t)sq0 * TLEN + tn) * 800 + dir * 400 + tid;
            p0 = __ldg(&P[base]);
            p1 = __ldg(&P[base + 1 * TLEN * 800]);
            p2 = __ldg(&P[base + 2 * TLEN * 800]);
            p3 = __ldg(&P[base + 3 * TLEN * 800]);
        }
#pragma unroll
        for (int kq = 0; kq < 25; kq++) {
            float4 w = sW4[kq];
            float4 h0 = sH4[kq], h1 = sH4[25 + kq], h2 = sH4[50 + kq], h3 = sH4[75 + kq];
            acc0 += w.x * h0.x + w.y * h0.y + w.z * h0.z + w.w * h0.w;
            acc1 += w.x * h1.x + w.y * h1.y + w.z * h1.z + w.w * h1.w;
            acc2 += w.x * h2.x + w.y * h2.y + w.z * h2.z + w.w * h2.w;
            acc3 += w.x * h3.x + w.y * h3.y + w.z * h3.z + w.w * h3.w;
        }
        sG[tid] = acc0; sG[400 + tid] = acc1; sG[800 + tid] = acc2; sG[1200 + tid] = acc3;
        __syncthreads();
        {
            float gi = sG[sPW * 400 + jPW];
            float gf = sG[sPW * 400 + 100 + jPW];
            float gg = sG[sPW * 400 + 200 + jPW];
            float go = sG[sPW * 400 + 300 + jPW];
            float c  = sC[sPW * 100 + jPW];
            float cn = sigf(gf) * c + sigf(gi) * tanh_acc(gg);
            float hn = sigf(go) * tanh_acc(cn);
            float outv = 0.0f;
            if (t < myLen) {
                sC[sPW * 100 + jPW] = cn;
                sH[sPW * 100 + jPW] = hn;
                outv = hn;
            }
            Y[((size_t)(sq0 + sPW) * TLEN + t) * ENCD + dir * 100 + jPW] = outv;
        }
        __syncthreads();
    }
}

// ---------------------------------------------------------------------------
__global__ __launch_bounds__(200) void meanpool(
    const float* __restrict__ Y, const int* __restrict__ lengths,
    float* __restrict__ enc)
{
    int s = blockIdx.x, e = threadIdx.x;
    const float* p = Y + (size_t)s * TLEN * ENCD + e;
    float sum = 0.0f;
#pragma unroll
    for (int t = 0; t < TLEN; t++) sum += p[t * ENCD];
    enc[s * ENCD + e] = sum / (float)__ldg(&lengths[s]);
}

// ---------------------------------------------------------------------------
// Parser: 2-CTA cluster, unit-partitioned TreeLSTM GEMV (250 Wt rows per CTA,
// fully smem-resident). One mbarrier full-barrier per step; decision is
// replicated; merged h,c exchanged via DSMEM stores.
// ---------------------------------------------------------------------------
#define PRS_WT    0
#define PRS_WA    50000
#define PRS_BT    51200
#define PRS_BUF   51452
#define PRS_G     52652
#define PRS_MISS  52904
#define PRS_SC    53104
#define PRS_MBAR  53108
#define PRS_TOTAL 53112
#define PR_THREADS 576

__global__ __cluster_dims__(2, 1, 1) __launch_bounds__(PR_THREADS, 1) void parser2(
    const float* __restrict__ missing, const float* __restrict__ Wa,
    const float* __restrict__ ba, const float* __restrict__ Wt,
    const float* __restrict__ bt, float* __restrict__ out)
{
    extern __shared__ float sm[];
    float* sWt   = sm + PRS_WT;
    float* sWa   = sm + PRS_WA;
    float* sBt   = sm + PRS_BT;
    float* sBuf  = sm + PRS_BUF;
    float* sG    = sm + PRS_G;
    float* sMiss = sm + PRS_MISS;
    float* sSc   = sm + PRS_SC;

    const int tid = threadIdx.x;
    const unsigned int rank = ctarank();
    const unsigned int peer = rank ^ 1u;
    const unsigned int mbarA = smem_u32(sm + PRS_MBAR);
    const unsigned int sBufA = smem_u32(sBuf);

    // load own Wt rows: local row r -> global row (r/50)*100 + rank*50 + (r%50)
    for (int i = tid; i < 50000; i += PR_THREADS) {
        int r = i / 200, k = i - r * 200;
        int grow = (r / 50) * 100 + (int)rank * 50 + (r % 50);
        sWt[i] = __ldg(&Wt[grow * 200 + k]);
    }
    for (int i = tid; i < 1200; i += PR_THREADS) sWa[i] = __ldg(&Wa[i]);
    if (tid < 250) {
        int grow = (tid / 50) * 100 + (int)rank * 50 + (tid % 50);
        sBt[tid] = __ldg(&bt[grow]);
    }
    if (tid < 200) {
        float mv = __ldg(&missing[tid]);
        sMiss[tid] = mv;
        sBuf[0 * 200 + tid] = mv;                    // i1 = missing
        sBuf[1 * 200 + tid] = mv;                    // i0 = missing
        sBuf[2 * 200 + tid] = __ldg(&g_enc[tid]);    // ib = enc[0]
    }
    const float ba0 = __ldg(&ba[0]), ba1 = __ldg(&ba[1]);
    if (tid == 0) mbar_init(mbarA, 2);
    __syncthreads();
    asm volatile("barrier.cluster.arrive.aligned;" ::: "memory");
    asm volatile("barrier.cluster.wait.aligned;"   ::: "memory");

    int i1 = 0, i0 = 1, ib = 2, ipre = 3, ibn = 4, isp = 5;
    int sp = 0, bp = 0;
    const int warp = tid >> 5;

    for (int step = 0; step < 2 * NSEQ - 1; step++) {
        // ---- prefetch warp (warp 17): stack[sp-3] -> ipre, enc[bp+1] -> ibn ----
        if (warp == 17) {
            int lane = tid - 544;
            float4* dpre = (float4*)(sBuf + ipre * 200);
            float4* dbn  = (float4*)(sBuf + ibn  * 200);
            const float4* mi4 = (const float4*)sMiss;
            for (int q = lane; q < 50; q += 32)
                dpre[q] = (sp >= 3) ? ldcg4(&g_stk[(sp - 3) * ENCD + 4 * q]) : mi4[q];
            int nbp = bp + 1;
            for (int q = lane; q < 50; q += 32)
                dbn[q] = (nbp < NSEQ) ? __ldg(((const float4*)(g_enc + nbp * ENCD)) + q)
                                      : mi4[q];
        }
        // ---- score warp (warp 16): 2x600 GEMV, replicated ----
        if (warp == 16) {
            int lane = tid - 512;
            const float* w0 = sWa;
            const float* w1 = sWa + 600;
            const float* f1p = sBuf + i1 * 200;
            const float* f0p = sBuf + i0 * 200;
            const float* fbp = sBuf + ib * 200;
            float a0 = 0.0f, a1 = 0.0f;
#pragma unroll
            for (int k = 0; k < 7; k++) {
                int kk = lane + 32 * k;
                if (kk < 200) { float f = f1p[kk]; a0 += w0[kk] * f;       a1 += w1[kk] * f; }
            }
#pragma unroll
            for (int k = 0; k < 7; k++) {
                int kk = lane + 32 * k;
                if (kk < 200) { float f = f0p[kk]; a0 += w0[200 + kk] * f; a1 += w1[200 + kk] * f; }
            }
#pragma unroll
            for (int k = 0; k < 7; k++) {
                int kk = lane + 32 * k;
                if (kk < 200) { float f = fbp[kk]; a0 += w0[400 + kk] * f; a1 += w1[400 + kk] * f; }
            }
#pragma unroll
            for (int o = 16; o > 0; o >>= 1) {
                a0 += __shfl_down_sync(0xffffffffu, a0, o);
                a1 += __shfl_down_sync(0xffffffffu, a1, o);
            }
            if (lane == 0) { sSc[0] = a0 + ba0; sSc[1] = a1 + ba1; }
        }
        __syncthreads();

        float m0 = (bp < NSEQ) ? sSc[0] : -1e30f;
        float m1 = (sp >= 2)   ? sSc[1] : -1e30f;
        bool is_shift = (m0 >= m1);   // argmax, first-index tie-break

        if (is_shift) {
            // push b: each CTA writes its own half [rank*100, rank*100+100)
            if (tid < 25) {
                float4 v = ((const float4*)(sBuf + ib * 200 + (int)rank * 100))[tid];
                stcg4(&g_stk[sp * ENCD + (int)rank * 100 + 4 * tid], v);
            }
        } else {
            // ---- TreeLSTM gate GEMV over own 250 rows (2 threads/row) ----
            if (tid < 500) {
                int r = tid >> 1, ph = tid & 1;
                const float4* wp4 = (const float4*)(sWt + r * 200 + ph * 100);
                const float4* xp  = (const float4*)(sBuf + (ph ? i0 : i1) * 200);
                float acc = 0.0f;
#pragma unroll
                for (int q = 0; q < 25; q++) {
                    float4 w = wp4[q], x = xp[q];
                    acc += w.x * x.x + w.y * x.y + w.z * x.z + w.w * x.w;
                }
                unsigned msk = __activemask();
                acc += __shfl_xor_sync(msk, acc, 1);
                if (!ph) sG[r] = acc + sBt[r];
            }
            __syncthreads();
            if (tid < 50) {
                int u = tid;
                int j = (int)rank * 50 + u;
                float gi = sG[u],        gf1 = sG[50 + u], gf2 = sG[100 + u];
                float go = sG[150 + u],  gu  = sG[200 + u];
                float c1 = sBuf[i1 * 200 + 100 + j];
                float c2 = sBuf[i0 * 200 + 100 + j];
                float c = sigf(gf1) * c1 + sigf(gf2) * c2 + sigf(gi) * tanh_acc(gu);
                float h = sigf(go) * tanh_acc(c);
                sBuf[isp * 200 + j]       = h;
                sBuf[isp * 200 + 100 + j] = c;
                st_remote_f32(sBufA + (unsigned int)(isp * 200 + j) * 4u,       peer, h);
                st_remote_f32(sBufA + (unsigned int)(isp * 200 + 100 + j) * 4u, peer, c);
                stcg(&g_stk[(sp - 2) * ENCD + j], h);
                stcg(&g_stk[(sp - 2) * ENCD + 100 + j], c);
            }
        }
        __syncthreads();
        if (tid == 0) {
            asm volatile("fence.acq_rel.cluster;" ::: "memory");
            mbar_arrive_local(mbarA);
            mbar_arrive_remote(mbarA, peer);
        }
        mbar_wait(mbarA, (unsigned int)(step & 1));

        // ---- rotate ring indices (uniform) ----
        if (is_shift) {
            int t = i1; i1 = i0; i0 = ib; ib = ibn; ibn = t;
            sp += 1; bp += 1;
        } else {
            int n1 = ipre, n0 = isp;
            ipre = i1; isp = i0;
            i1 = n1; i0 = n0;
            sp -= 1;
        }
    }

    if (rank == 0 && tid < 50) {
        float4 v = ldcg4(&g_stk[4 * tid]);
        ((float4*)out)[tid] = v;
    }
}

// ---------------------------------------------------------------------------
extern "C" void kernel_launch(void* const* d_in, const int* in_sizes, int n_in,
                              void* d_out, int out_size)
{
    const int*   tokens  = (const int*)d_in[0];
    const int*   lengths = (const int*)d_in[1];
    const float* emb     = (const float*)d_in[2];
    const float* Wih0    = (const float*)d_in[3];
    const float* Whh0    = (const float*)d_in[4];
    const float* b0      = (const float*)d_in[5];
    const float* Wih12   = (const float*)d_in[6];
    const float* Whh12   = (const float*)d_in[7];
    const float* b12     = (const float*)d_in[8];
    const float* missing = (const float*)d_in[9];
    const float* Wa      = (const float*)d_in[10];
    const float* ba      = (const float*)d_in[11];
    const float* Wt      = (const float*)d_in[12];
    const float* bt      = (const float*)d_in[13];
    float* out = (float*)d_out;

    float *P, *Ya, *Yb, *enc;
    cudaGetSymbolAddress((void**)&P,  g_P);
    cudaGetSymbolAddress((void**)&Ya, g_Ya);
    cudaGetSymbolAddress((void**)&Yb, g_Yb);
    cudaGetSymbolAddress((void**)&enc, g_enc);

    const int lstmSmem = (40000 + 400 + 400 + 1600) * 4;   // 169600
    const int parsSmem = PRS_TOTAL * 4;                    // 212448
    cudaFuncSetAttribute(lstm_rec, cudaFuncAttributeMaxDynamicSharedMemorySize, lstmSmem);
    cudaFuncSetAttribute(parser2, cudaFuncAttributeMaxDynamicSharedMemorySize, parsSmem);

    dim3 gg(128, 10), rg(64, 2);

    // layer 0
    proj_gemm<<<gg, 256>>>(emb, tokens, Wih0, b0, P, 300);
    lstm_rec<<<rg, 400, lstmSmem>>>(P, Whh0, lengths, Ya);
    // layer 1
    proj_gemm<<<gg, 256>>>(Ya, nullptr, Wih12, b12, P, 200);
    lstm_rec<<<rg, 400, lstmSmem>>>(P, Whh12, lengths, Yb);
    // layer 2
    proj_gemm<<<gg, 256>>>(Yb, nullptr, Wih12 + 160000, b12 + 800, P, 200);
    lstm_rec<<<rg, 400, lstmSmem>>>(P, Whh12 + 80000, lengths, Ya);
    // pool + parse
    meanpool<<<NSEQ, 200>>>(Ya, lengths, enc);
    parser2<<<2, PR_THREADS, parsSmem>>>(missing, Wa, ba, Wt, bt, out);
}

// round 6
// speedup vs baseline: 1.3720x; 1.1605x over previous
#include <cuda_runtime.h>
#include <stdint.h>
#include <math.h>

#define NSEQ 256
#define TLEN 32
#define MROWS 8192      // NSEQ*TLEN
#define ENCD 200

// scratch (static device allocations are allowed)
__device__ float g_P  [MROWS * 800];
__device__ float g_Ya [MROWS * ENCD];
__device__ float g_Yb [MROWS * ENCD];
__device__ float g_enc[NSEQ * ENCD];
__device__ float g_stk[NSEQ * ENCD];

__device__ __forceinline__ float sigf(float x) { return 1.0f / (1.0f + expf(-x)); }
// accurate tanh via expf (robust even under fast-math)
__device__ __forceinline__ float tanh_acc(float x) {
    float e = expf(-2.0f * fabsf(x));
    float r = (1.0f - e) / (1.0f + e);
    return x >= 0.0f ? r : -r;
}
__device__ __forceinline__ float4 ldcg4(const float* p) {
    float4 v;
    asm volatile("ld.global.cg.v4.f32 {%0,%1,%2,%3}, [%4];"
                 : "=f"(v.x), "=f"(v.y), "=f"(v.z), "=f"(v.w) : "l"(p));
    return v;
}
__device__ __forceinline__ void stcg(float* p, float v) {
    asm volatile("st.global.cg.f32 [%0], %1;" :: "l"(p), "f"(v));
}
__device__ __forceinline__ void stcg2(float* p, float2 v) {
    asm volatile("st.global.cg.v2.f32 [%0], {%1,%2};"
                 :: "l"(p), "f"(v.x), "f"(v.y));
}
__device__ __forceinline__ unsigned int smem_u32(const void* p) {
    unsigned int a;
    asm("{ .reg .u64 t; cvta.to.shared.u64 t, %1; cvt.u32.u64 %0, t; }"
        : "=r"(a) : "l"(p));
    return a;
}
__device__ __forceinline__ unsigned int ctarank() {
    unsigned int r; asm("mov.u32 %0, %%cluster_ctarank;" : "=r"(r)); return r;
}
__device__ __forceinline__ void st_remote_f32(unsigned int laddr, unsigned int rk, float v) {
    asm volatile(
        "{ .reg .b32 ra; mapa.shared::cluster.u32 ra, %0, %1; "
        "st.shared::cluster.f32 [ra], %2; }"
        :: "r"(laddr), "r"(rk), "f"(v) : "memory");
}
__device__ __forceinline__ void mbar_init(unsigned int addr, unsigned int count) {
    asm volatile("mbarrier.init.shared.b64 [%0], %1;" :: "r"(addr), "r"(count) : "memory");
}
// remote (or self) arrive, release.cluster semantics
__device__ __forceinline__ void mbar_arrive_rank(unsigned int laddr, unsigned int rk) {
    asm volatile(
        "{ .reg .b32 ra; mapa.shared::cluster.u32 ra, %0, %1; "
        "mbarrier.arrive.shared::cluster.b64 _, [ra]; }"
        :: "r"(laddr), "r"(rk) : "memory");
}
// acquire at CLUSTER scope folded into the wait — no separate fences needed
__device__ __forceinline__ void mbar_wait_cl(unsigned int addr, unsigned int parity) {
    asm volatile(
        "{\n\t.reg .pred P1;\n\t"
        "WL%=:\n\t"
        "mbarrier.try_wait.parity.acquire.cluster.shared::cta.b64 P1, [%0], %1, 0x989680;\n\t"
        "@P1 bra.uni WD%=;\n\t"
        "bra.uni WL%=;\n\t"
        "WD%=:\n\t}"
        :: "r"(addr), "r"(parity) : "memory");
}

// ---------------------------------------------------------------------------
// P[m][800] = A[row(m)][0:K] @ W[n][0:K]^T + bias[n]
// ---------------------------------------------------------------------------
__global__ __launch_bounds__(256) void proj_gemm(
    const float* __restrict__ Asrc, const int* __restrict__ tok,
    const float* __restrict__ W, const float* __restrict__ bias,
    float* __restrict__ P, int K)
{
    __shared__ float As[20 * 68];
    __shared__ float Ws[20 * 80];
    __shared__ unsigned long long roff[64];

    const int tid = threadIdx.x;
    const int M0 = blockIdx.x * 64;
    const int N0 = blockIdx.y * 80;

    if (tid < 64) {
        long long o = tok ? (long long)__ldg(&tok[M0 + tid]) * (long long)K
                          : (long long)(M0 + tid) * (long long)K;
        roff[tid] = (unsigned long long)o;
    }
    const int m0 = (tid >> 4) * 4;
    const int n0 = (tid & 15) * 5;

    float acc[4][5];
#pragma unroll
    for (int i = 0; i < 4; i++)
#pragma unroll
        for (int j = 0; j < 5; j++) acc[i][j] = 0.0f;
    __syncthreads();

    for (int kt = 0; kt < K; kt += 20) {
        {
            int i0 = tid * 5;
            int mm = i0 / 20, kk = i0 % 20;
            const float* ap = Asrc + roff[mm] + kt + kk;
#pragma unroll
            for (int q = 0; q < 5; q++) As[(kk + q) * 68 + mm] = ap[q];
        }
        for (int i = tid; i < 1600; i += 256) {
            int nn = i / 20, kk = i % 20;
            Ws[kk * 80 + nn] = __ldg(&W[(size_t)(N0 + nn) * K + kt + kk]);
        }
        __syncthreads();
#pragma unroll
        for (int kk = 0; kk < 20; kk++) {
            float4 a4 = *(const float4*)&As[kk * 68 + m0];
            float a[4] = {a4.x, a4.y, a4.z, a4.w};
            float b[5];
#pragma unroll
            for (int j = 0; j < 5; j++) b[j] = Ws[kk * 80 + n0 + j];
#pragma unroll
            for (int i = 0; i < 4; i++)
#pragma unroll
                for (int j = 0; j < 5; j++) acc[i][j] += a[i] * b[j];
        }
        __syncthreads();
    }
#pragma unroll
    for (int i = 0; i < 4; i++) {
        size_t row = (size_t)(M0 + m0 + i) * 800 + N0 + n0;
#pragma unroll
        for (int j = 0; j < 5; j++)
            P[row + j] = acc[i][j] + __ldg(&bias[N0 + n0 + j]);
    }
}

// ---------------------------------------------------------------------------
// LSTM recurrence: 800 threads, 2-way k-split per gate row (shfl combine).
// ---------------------------------------------------------------------------
__global__ __launch_bounds__(800, 1) void lstm_rec(
    const float* __restrict__ P, const float* __restrict__ Whh2,
    const int* __restrict__ lengths, float* __restrict__ Y)
{
    extern __shared__ float sm[];
    float* sW = sm;             // 40000
    float* sH = sm + 40000;     // 400
    float* sC = sH + 400;       // 400
    float* sG = sC + 400;       // 1600

    const int tid = threadIdx.x;
    const int dir = blockIdx.y;
    const int sq0 = blockIdx.x * 4;

    const float* Wd = Whh2 + dir * 40000;
    for (int i = tid; i < 40000; i += 800) sW[i] = Wd[i];
    if (tid < 800 && tid >= 0) { if (tid < 800) {} }
    for (int i = tid; i < 800; i += 800) sm[40000 + i] = 0.0f;

    const int r  = tid >> 1;      // gate row 0..399
    const int ph = tid & 1;       // k-half
    const int sPW = (tid < 400) ? (tid / 100) : 0;
    const int jPW = (tid < 400) ? (tid % 100) : 0;
    const int myLen = (tid < 400) ? __ldg(&lengths[sq0 + sPW]) : 0;
    __syncthreads();

    const float4* wb = (const float4*)(sW + r * 100);
    const float4* sH4 = (const float4*)sH;

    // preload P seeds (2 per thread)
    float pA, pB;
    {
        int t = dir ? (TLEN - 1) : 0;
        size_t base = ((size_t)sq0 * TLEN + t) * 800 + dir * 400 + r;
        if (ph == 0) { pA = __ldg(&P[base]);
                       pB = __ldg(&P[base + 1 * TLEN * 800]); }
        else         { pA = __ldg(&P[base + 2 * TLEN * 800]);
                       pB = __ldg(&P[base + 3 * TLEN * 800]); }
    }

    for (int st = 0; st < TLEN; st++) {
        int t = dir ? (TLEN - 1 - st) : st;
        float acc0, acc1, acc2, acc3;
        if (ph == 0) { acc0 = pA; acc1 = pB; acc2 = 0.f; acc3 = 0.f; }
        else         { acc0 = 0.f; acc1 = 0.f; acc2 = pA; acc3 = pB; }
        if (st + 1 < TLEN) {
            int tn = dir ? (TLEN - 2 - st) : (st + 1);
            size_t base = ((size_t)sq0 * TLEN + tn) * 800 + dir * 400 + r;
            if (ph == 0) { pA = __ldg(&P[base]);
                           pB = __ldg(&P[base + 1 * TLEN * 800]); }
            else         { pA = __ldg(&P[base + 2 * TLEN * 800]);
                           pB = __ldg(&P[base + 3 * TLEN * 800]); }
        }
        if (ph == 0) {
#pragma unroll
            for (int q = 0; q < 12; q++) {
                float4 w = wb[q];
                float4 h0 = sH4[q], h1 = sH4[25 + q], h2 = sH4[50 + q], h3 = sH4[75 + q];
                acc0 += w.x*h0.x + w.y*h0.y + w.z*h0.z + w.w*h0.w;
                acc1 += w.x*h1.x + w.y*h1.y + w.z*h1.z + w.w*h1.w;
                acc2 += w.x*h2.x + w.y*h2.y + w.z*h2.z + w.w*h2.w;
                acc3 += w.x*h3.x + w.y*h3.y + w.z*h3.z + w.w*h3.w;
            }
        } else {
#pragma unroll
            for (int q = 12; q < 25; q++) {
                float4 w = wb[q];
                float4 h0 = sH4[q], h1 = sH4[25 + q], h2 = sH4[50 + q], h3 = sH4[75 + q];
                acc0 += w.x*h0.x + w.y*h0.y + w.z*h0.z + w.w*h0.w;
                acc1 += w.x*h1.x + w.y*h1.y + w.z*h1.z + w.w*h1.w;
                acc2 += w.x*h2.x + w.y*h2.y + w.z*h2.z + w.w*h2.w;
                acc3 += w.x*h3.x + w.y*h3.y + w.z*h3.z + w.w*h3.w;
            }
        }
        acc0 += __shfl_xor_sync(0xffffffffu, acc0, 1);
        acc1 += __shfl_xor_sync(0xffffffffu, acc1, 1);
        acc2 += __shfl_xor_sync(0xffffffffu, acc2, 1);
        acc3 += __shfl_xor_sync(0xffffffffu, acc3, 1);
        if (ph == 0) {
            sG[r] = acc0; sG[400 + r] = acc1; sG[800 + r] = acc2; sG[1200 + r] = acc3;
        }
        __syncthreads();
        if (tid < 400) {
            float gi = sG[sPW * 400 + jPW];
            float gf = sG[sPW * 400 + 100 + jPW];
            float gg = sG[sPW * 400 + 200 + jPW];
            float go = sG[sPW * 400 + 300 + jPW];
            float c  = sC[sPW * 100 + jPW];
            float cn = sigf(gf) * c + sigf(gi) * tanh_acc(gg);
            float hn = sigf(go) * tanh_acc(cn);
            float outv = 0.0f;
            if (t < myLen) {
                sC[sPW * 100 + jPW] = cn;
                sH[sPW * 100 + jPW] = hn;
                outv = hn;
            }
            Y[((size_t)(sq0 + sPW) * TLEN + t) * ENCD + dir * 100 + jPW] = outv;
        }
        __syncthreads();
    }
}

// ---------------------------------------------------------------------------
__global__ __launch_bounds__(200) void meanpool(
    const float* __restrict__ Y, const int* __restrict__ lengths,
    float* __restrict__ enc)
{
    int s = blockIdx.x, e = threadIdx.x;
    const float* p = Y + (size_t)s * TLEN * ENCD + e;
    float sum = 0.0f;
#pragma unroll
    for (int t = 0; t < TLEN; t++) sum += p[t * ENCD];
    enc[s * ENCD + e] = sum / (float)__ldg(&lengths[s]);
}

// ---------------------------------------------------------------------------
// Parser: 4-CTA cluster. CTA rank owns units [rank*25, rank*25+25): 125 Wt
// rows (100 KB) smem-resident. Per step: one mbarrier (count=4), arrives are
// release.cluster, waits acquire.cluster — NO explicit fences, NO L1 flushes.
// Merged h,c pushed to all peers via DSMEM.
// ---------------------------------------------------------------------------
#define PRS_WT    0
#define PRS_WA    25000
#define PRS_BT    26200
#define PRS_BUF   26328
#define PRS_G     27528
#define PRS_MISS  27656
#define PRS_SC    27856
#define PRS_MBAR  27860
#define PRS_TOTAL 27864
#define PR_THREADS 320
#define PCLUSTER 4

__global__ __cluster_dims__(PCLUSTER, 1, 1) __launch_bounds__(PR_THREADS, 1) void parser4(
    const float* __restrict__ missing, const float* __restrict__ Wa,
    const float* __restrict__ ba, const float* __restrict__ Wt,
    const float* __restrict__ bt, float* __restrict__ out)
{
    extern __shared__ float sm[];
    float* sWt   = sm + PRS_WT;    // 125 rows x 200
    float* sWa   = sm + PRS_WA;    // 1200
    float* sBt   = sm + PRS_BT;    // 125
    float* sBuf  = sm + PRS_BUF;   // 6 x 200
    float* sG    = sm + PRS_G;     // 125
    float* sMiss = sm + PRS_MISS;  // 200
    float* sSc   = sm + PRS_SC;    // 2
    const int tid = threadIdx.x;
    const unsigned int rank = ctarank();
    const unsigned int mbarA = smem_u32(sm + PRS_MBAR);
    const unsigned int sBufA = smem_u32(sBuf);

    // own Wt rows: local row r (0..124): gate g=r/25, unit u=r%25
    //   global row = g*100 + rank*25 + u
    for (int i = tid; i < 125 * 200; i += PR_THREADS) {
        int r = i / 200, k = i - r * 200;
        int grow = (r / 25) * 100 + (int)rank * 25 + (r % 25);
        sWt[i] = __ldg(&Wt[grow * 200 + k]);
    }
    for (int i = tid; i < 1200; i += PR_THREADS) sWa[i] = __ldg(&Wa[i]);
    if (tid < 125) {
        int grow = (tid / 25) * 100 + (int)rank * 25 + (tid % 25);
        sBt[tid] = __ldg(&bt[grow]);
    }
    if (tid < 200) {
        float mv = __ldg(&missing[tid]);
        sMiss[tid] = mv;
        sBuf[0 * 200 + tid] = mv;                    // i1 = missing
        sBuf[1 * 200 + tid] = mv;                    // i0 = missing
        sBuf[2 * 200 + tid] = __ldg(&g_enc[tid]);    // ib = enc[0]
    }
    const float ba0 = __ldg(&ba[0]), ba1 = __ldg(&ba[1]);
    if (tid == 0) mbar_init(mbarA, PCLUSTER);
    __syncthreads();
    asm volatile("barrier.cluster.arrive.aligned;" ::: "memory");
    asm volatile("barrier.cluster.wait.aligned;"   ::: "memory");

    int i1 = 0, i0 = 1, ib = 2, ipre = 3, ibn = 4, isp = 5;
    int sp = 0, bp = 0;
    const int warp = tid >> 5;

    for (int step = 0; step < 2 * NSEQ - 1; step++) {
        // ---- prefetch warp (warp 9): stack[sp-3] -> ipre, enc[bp+1] -> ibn ----
        if (warp == 9) {
            int lane = tid - 288;
            float4* dpre = (float4*)(sBuf + ipre * 200);
            float4* dbn  = (float4*)(sBuf + ibn  * 200);
            const float4* mi4 = (const float4*)sMiss;
            for (int q = lane; q < 50; q += 32)
                dpre[q] = (sp >= 3) ? ldcg4(&g_stk[(sp - 3) * ENCD + 4 * q]) : mi4[q];
            int nbp = bp + 1;
            for (int q = lane; q < 50; q += 32)
                dbn[q] = (nbp < NSEQ) ? __ldg(((const float4*)(g_enc + nbp * ENCD)) + q)
                                      : mi4[q];
        }
        // ---- score warp (warp 8): 2x600 GEMV, replicated in every CTA ----
        if (warp == 8) {
            int lane = tid - 256;
            const float* w0 = sWa;
            const float* w1 = sWa + 600;
            const float* f1p = sBuf + i1 * 200;
            const float* f0p = sBuf + i0 * 200;
            const float* fbp = sBuf + ib * 200;
            float a0 = 0.0f, a1 = 0.0f;
#pragma unroll
            for (int k = 0; k < 7; k++) {
                int kk = lane + 32 * k;
                if (kk < 200) { float f = f1p[kk]; a0 += w0[kk] * f;       a1 += w1[kk] * f; }
            }
#pragma unroll
            for (int k = 0; k < 7; k++) {
                int kk = lane + 32 * k;
                if (kk < 200) { float f = f0p[kk]; a0 += w0[200 + kk] * f; a1 += w1[200 + kk] * f; }
            }
#pragma unroll
            for (int k = 0; k < 7; k++) {
                int kk = lane + 32 * k;
                if (kk < 200) { float f = fbp[kk]; a0 += w0[400 + kk] * f; a1 += w1[400 + kk] * f; }
            }
#pragma unroll
            for (int o = 16; o > 0; o >>= 1) {
                a0 += __shfl_down_sync(0xffffffffu, a0, o);
                a1 += __shfl_down_sync(0xffffffffu, a1, o);
            }
            if (lane == 0) { sSc[0] = a0 + ba0; sSc[1] = a1 + ba1; }
        }
        __syncthreads();

        float m0 = (bp < NSEQ) ? sSc[0] : -1e30f;
        float m1 = (sp >= 2)   ? sSc[1] : -1e30f;
        bool is_shift = (m0 >= m1);   // argmax, first-index tie-break

        if (is_shift) {
            // push b: CTA writes its 50-float quarter [rank*50, rank*50+50)
            if (tid < 25) {
                const float2* src = (const float2*)(sBuf + ib * 200 + (int)rank * 50);
                stcg2(&g_stk[sp * ENCD + (int)rank * 50 + 2 * tid], src[tid]);
            }
        } else {
            // ---- TreeLSTM gate GEMV over own 125 rows (2 threads/row) ----
            if (tid < 250) {
                int r = tid >> 1, ph = tid & 1;
                const float4* wp4 = (const float4*)(sWt + r * 200 + ph * 100);
                const float4* xp  = (const float4*)(sBuf + (ph ? i0 : i1) * 200);
                float acc = 0.0f;
#pragma unroll
                for (int q = 0; q < 25; q++) {
                    float4 w = wp4[q], x = xp[q];
                    acc += w.x * x.x + w.y * x.y + w.z * x.z + w.w * x.w;
                }
                unsigned msk = __activemask();
                acc += __shfl_xor_sync(msk, acc, 1);
                if (!ph) sG[r] = acc + sBt[r];
            }
            __syncthreads();
            if (tid < 25) {
                int u = tid;
                int j = (int)rank * 25 + u;
                float gi = sG[u],        gf1 = sG[25 + u], gf2 = sG[50 + u];
                float go = sG[75 + u],   gu  = sG[100 + u];
                float c1 = sBuf[i1 * 200 + 100 + j];
                float c2 = sBuf[i0 * 200 + 100 + j];
                float c = sigf(gf1) * c1 + sigf(gf2) * c2 + sigf(gi) * tanh_acc(gu);
                float h = sigf(go) * tanh_acc(c);
                sBuf[isp * 200 + j]       = h;
                sBuf[isp * 200 + 100 + j] = c;
                unsigned int ah = sBufA + (unsigned int)(isp * 200 + j) * 4u;
                unsigned int ac = sBufA + (unsigned int)(isp * 200 + 100 + j) * 4u;
#pragma unroll
                for (unsigned int rk = 0; rk < PCLUSTER; rk++) {
                    if (rk != rank) { st_remote_f32(ah, rk, h); st_remote_f32(ac, rk, c); }
                }
                stcg(&g_stk[(sp - 2) * ENCD + j], h);
                stcg(&g_stk[(sp - 2) * ENCD + 100 + j], c);
            }
        }
        __syncthreads();
        if (tid == 0) {
#pragma unroll
            for (unsigned int rk = 0; rk < PCLUSTER; rk++) mbar_arrive_rank(mbarA, rk);
        }
        mbar_wait_cl(mbarA, (unsigned int)(step & 1));

        // ---- rotate ring indices (uniform across CTAs) ----
        if (is_shift) {
            int t = i1; i1 = i0; i0 = ib; ib = ibn; ibn = t;
            sp += 1; bp += 1;
        } else {
            int n1 = ipre, n0 = isp;
            ipre = i1; isp = i0;
            i1 = n1; i0 = n0;
            sp -= 1;
        }
    }

    if (rank == 0 && tid < 50) {
        float4 v = ldcg4(&g_stk[4 * tid]);
        ((float4*)out)[tid] = v;
    }
}

// ---------------------------------------------------------------------------
extern "C" void kernel_launch(void* const* d_in, const int* in_sizes, int n_in,
                              void* d_out, int out_size)
{
    const int*   tokens  = (const int*)d_in[0];
    const int*   lengths = (const int*)d_in[1];
    const float* emb     = (const float*)d_in[2];
    const float* Wih0    = (const float*)d_in[3];
    const float* Whh0    = (const float*)d_in[4];
    const float* b0      = (const float*)d_in[5];
    const float* Wih12   = (const float*)d_in[6];
    const float* Whh12   = (const float*)d_in[7];
    const float* b12     = (const float*)d_in[8];
    const float* missing = (const float*)d_in[9];
    const float* Wa      = (const float*)d_in[10];
    const float* ba      = (const float*)d_in[11];
    const float* Wt      = (const float*)d_in[12];
    const float* bt      = (const float*)d_in[13];
    float* out = (float*)d_out;

    float *P, *Ya, *Yb, *enc;
    cudaGetSymbolAddress((void**)&P,  g_P);
    cudaGetSymbolAddress((void**)&Ya, g_Ya);
    cudaGetSymbolAddress((void**)&Yb, g_Yb);
    cudaGetSymbolAddress((void**)&enc, g_enc);

    const int lstmSmem = (40000 + 400 + 400 + 1600) * 4;   // 169600
    const int parsSmem = PRS_TOTAL * 4;                    // 111456
    cudaFuncSetAttribute(lstm_rec, cudaFuncAttributeMaxDynamicSharedMemorySize, lstmSmem);
    cudaFuncSetAttribute(parser4, cudaFuncAttributeMaxDynamicSharedMemorySize, parsSmem);

    dim3 gg(128, 10), rg(64, 2);

    // layer 0
    proj_gemm<<<gg, 256>>>(emb, tokens, Wih0, b0, P, 300);
    lstm_rec<<<rg, 800, lstmSmem>>>(P, Whh0, lengths, Ya);
    // layer 1
    proj_gemm<<<gg, 256>>>(Ya, nullptr, Wih12, b12, P, 200);
    lstm_rec<<<rg, 800, lstmSmem>>>(P, Whh12, lengths, Yb);
    // layer 2
    proj_gemm<<<gg, 256>>>(Yb, nullptr, Wih12 + 160000, b12 + 800, P, 200);
    lstm_rec<<<rg, 800, lstmSmem>>>(P, Whh12 + 80000, lengths, Ya);
    // pool + parse
    meanpool<<<NSEQ, 200>>>(Ya, lengths, enc);
    parser4<<<PCLUSTER, PR_THREADS, parsSmem>>>(missing, Wa, ba, Wt, bt, out);
}

// round 7
// speedup vs baseline: 1.5171x; 1.1058x over previous
#include <cuda_runtime.h>
#include <stdint.h>
#include <math.h>

#define NSEQ 256
#define TLEN 32
#define MROWS 8192      // NSEQ*TLEN
#define ENCD 200

// scratch (static device allocations are allowed)
__device__ float g_P  [MROWS * 800];
__device__ float g_Ya [MROWS * ENCD];
__device__ float g_Yb [MROWS * ENCD];
__device__ float g_enc[NSEQ * ENCD];
__device__ float g_stk[NSEQ * ENCD];

__device__ __forceinline__ float sigf(float x) { return 1.0f / (1.0f + expf(-x)); }
// accurate tanh via expf (robust even under fast-math)
__device__ __forceinline__ float tanh_acc(float x) {
    float e = expf(-2.0f * fabsf(x));
    float r = (1.0f - e) / (1.0f + e);
    return x >= 0.0f ? r : -r;
}
__device__ __forceinline__ float4 ldcg4(const float* p) {
    float4 v;
    asm volatile("ld.global.cg.v4.f32 {%0,%1,%2,%3}, [%4];"
                 : "=f"(v.x), "=f"(v.y), "=f"(v.z), "=f"(v.w) : "l"(p));
    return v;
}
__device__ __forceinline__ void stcg(float* p, float v) {
    asm volatile("st.global.cg.f32 [%0], %1;" :: "l"(p), "f"(v));
}
__device__ __forceinline__ void stcg2(float* p, float2 v) {
    asm volatile("st.global.cg.v2.f32 [%0], {%1,%2};"
                 :: "l"(p), "f"(v.x), "f"(v.y));
}
__device__ __forceinline__ unsigned int smem_u32(const void* p) {
    unsigned int a;
    asm("{ .reg .u64 t; cvta.to.shared.u64 t, %1; cvt.u32.u64 %0, t; }"
        : "=r"(a) : "l"(p));
    return a;
}
__device__ __forceinline__ unsigned int ctarank() {
    unsigned int r; asm("mov.u32 %0, %%cluster_ctarank;" : "=r"(r)); return r;
}
__device__ __forceinline__ void st_remote_f32(unsigned int laddr, unsigned int rk, float v) {
    asm volatile(
        "{ .reg .b32 ra; mapa.shared::cluster.u32 ra, %0, %1; "
        "st.shared::cluster.f32 [ra], %2; }"
        :: "r"(laddr), "r"(rk), "f"(v) : "memory");
}
__device__ __forceinline__ void mbar_init(unsigned int addr, unsigned int count) {
    asm volatile("mbarrier.init.shared.b64 [%0], %1;" :: "r"(addr), "r"(count) : "memory");
}
// remote (or self) arrive, release.cluster semantics
__device__ __forceinline__ void mbar_arrive_rank(unsigned int laddr, unsigned int rk) {
    asm volatile(
        "{ .reg .b32 ra; mapa.shared::cluster.u32 ra, %0, %1; "
        "mbarrier.arrive.shared::cluster.b64 _, [ra]; }"
        :: "r"(laddr), "r"(rk) : "memory");
}
// acquire at CLUSTER scope folded into the wait — no separate fences needed
__device__ __forceinline__ void mbar_wait_cl(unsigned int addr, unsigned int parity) {
    asm volatile(
        "{\n\t.reg .pred P1;\n\t"
        "WL%=:\n\t"
        "mbarrier.try_wait.parity.acquire.cluster.shared::cta.b64 P1, [%0], %1, 0x989680;\n\t"
        "@P1 bra.uni WD%=;\n\t"
        "bra.uni WL%=;\n\t"
        "WD%=:\n\t}"
        :: "r"(addr), "r"(parity) : "memory");
}

// ---------------------------------------------------------------------------
// P[m][800] = A[row(m)][0:K] @ W[n][0:K]^T + bias[n]
// ---------------------------------------------------------------------------
__global__ __launch_bounds__(256) void proj_gemm(
    const float* __restrict__ Asrc, const int* __restrict__ tok,
    const float* __restrict__ W, const float* __restrict__ bias,
    float* __restrict__ P, int K)
{
    __shared__ float As[20 * 68];
    __shared__ float Ws[20 * 80];
    __shared__ unsigned long long roff[64];

    const int tid = threadIdx.x;
    const int M0 = blockIdx.x * 64;
    const int N0 = blockIdx.y * 80;

    if (tid < 64) {
        long long o = tok ? (long long)__ldg(&tok[M0 + tid]) * (long long)K
                          : (long long)(M0 + tid) * (long long)K;
        roff[tid] = (unsigned long long)o;
    }
    const int m0 = (tid >> 4) * 4;
    const int n0 = (tid & 15) * 5;

    float acc[4][5];
#pragma unroll
    for (int i = 0; i < 4; i++)
#pragma unroll
        for (int j = 0; j < 5; j++) acc[i][j] = 0.0f;
    __syncthreads();

    for (int kt = 0; kt < K; kt += 20) {
        {
            int i0 = tid * 5;
            int mm = i0 / 20, kk = i0 % 20;
            const float* ap = Asrc + roff[mm] + kt + kk;
#pragma unroll
            for (int q = 0; q < 5; q++) As[(kk + q) * 68 + mm] = ap[q];
        }
        for (int i = tid; i < 1600; i += 256) {
            int nn = i / 20, kk = i % 20;
            Ws[kk * 80 + nn] = __ldg(&W[(size_t)(N0 + nn) * K + kt + kk]);
        }
        __syncthreads();
#pragma unroll
        for (int kk = 0; kk < 20; kk++) {
            float4 a4 = *(const float4*)&As[kk * 68 + m0];
            float a[4] = {a4.x, a4.y, a4.z, a4.w};
            float b[5];
#pragma unroll
            for (int j = 0; j < 5; j++) b[j] = Ws[kk * 80 + n0 + j];
#pragma unroll
            for (int i = 0; i < 4; i++)
#pragma unroll
                for (int j = 0; j < 5; j++) acc[i][j] += a[i] * b[j];
        }
        __syncthreads();
    }
#pragma unroll
    for (int i = 0; i < 4; i++) {
        size_t row = (size_t)(M0 + m0 + i) * 800 + N0 + n0;
#pragma unroll
        for (int j = 0; j < 5; j++)
            P[row + j] = acc[i][j] + __ldg(&bias[N0 + n0 + j]);
    }
}

// ---------------------------------------------------------------------------
// LSTM recurrence (400 threads, pipelined P loads — best measured variant)
// ---------------------------------------------------------------------------
__global__ __launch_bounds__(400, 1) void lstm_rec(
    const float* __restrict__ P, const float* __restrict__ Whh2,
    const int* __restrict__ lengths, float* __restrict__ Y)
{
    extern __shared__ float sm[];
    float* sW = sm;
    float* sH = sm + 40000;
    float* sC = sH + 400;
    float* sG = sC + 400;

    const int tid = threadIdx.x;
    const int dir = blockIdx.y;
    const int sq0 = blockIdx.x * 4;

    const float* Wd = Whh2 + dir * 40000;
    for (int i = tid; i < 40000; i += 400) sW[i] = Wd[i];
    for (int i = tid; i < 800; i += 400) sm[40000 + i] = 0.0f;

    const int sPW = tid / 100;
    const int jPW = tid % 100;
    const int myLen = __ldg(&lengths[sq0 + sPW]);
    __syncthreads();

    const float4* sW4 = (const float4*)(sW + tid * 100);
    const float4* sH4 = (const float4*)sH;

    float p0, p1, p2, p3;
    {
        int t = dir ? (TLEN - 1) : 0;
        size_t base = ((size_t)sq0 * TLEN + t) * 800 + dir * 400 + tid;
        p0 = __ldg(&P[base]);
        p1 = __ldg(&P[base + 1 * TLEN * 800]);
        p2 = __ldg(&P[base + 2 * TLEN * 800]);
        p3 = __ldg(&P[base + 3 * TLEN * 800]);
    }

    for (int st = 0; st < TLEN; st++) {
        int t = dir ? (TLEN - 1 - st) : st;
        float acc0 = p0, acc1 = p1, acc2 = p2, acc3 = p3;
        if (st + 1 < TLEN) {
            int tn = dir ? (TLEN - 2 - st) : (st + 1);
            size_t base = ((size_t)sq0 * TLEN + tn) * 800 + dir * 400 + tid;
            p0 = __ldg(&P[base]);
            p1 = __ldg(&P[base + 1 * TLEN * 800]);
            p2 = __ldg(&P[base + 2 * TLEN * 800]);
            p3 = __ldg(&P[base + 3 * TLEN * 800]);
        }
#pragma unroll
        for (int kq = 0; kq < 25; kq++) {
            float4 w = sW4[kq];
            float4 h0 = sH4[kq], h1 = sH4[25 + kq], h2 = sH4[50 + kq], h3 = sH4[75 + kq];
            acc0 += w.x * h0.x + w.y * h0.y + w.z * h0.z + w.w * h0.w;
            acc1 += w.x * h1.x + w.y * h1.y + w.z * h1.z + w.w * h1.w;
            acc2 += w.x * h2.x + w.y * h2.y + w.z * h2.z + w.w * h2.w;
            acc3 += w.x * h3.x + w.y * h3.y + w.z * h3.z + w.w * h3.w;
        }
        sG[tid] = acc0; sG[400 + tid] = acc1; sG[800 + tid] = acc2; sG[1200 + tid] = acc3;
        __syncthreads();
        {
            float gi = sG[sPW * 400 + jPW];
            float gf = sG[sPW * 400 + 100 + jPW];
            float gg = sG[sPW * 400 + 200 + jPW];
            float go = sG[sPW * 400 + 300 + jPW];
            float c  = sC[sPW * 100 + jPW];
            float cn = sigf(gf) * c + sigf(gi) * tanh_acc(gg);
            float hn = sigf(go) * tanh_acc(cn);
            float outv = 0.0f;
            if (t < myLen) {
                sC[sPW * 100 + jPW] = cn;
                sH[sPW * 100 + jPW] = hn;
                outv = hn;
            }
            Y[((size_t)(sq0 + sPW) * TLEN + t) * ENCD + dir * 100 + jPW] = outv;
        }
        __syncthreads();
    }
}

// ---------------------------------------------------------------------------
__global__ __launch_bounds__(200) void meanpool(
    const float* __restrict__ Y, const int* __restrict__ lengths,
    float* __restrict__ enc)
{
    int s = blockIdx.x, e = threadIdx.x;
    const float* p = Y + (size_t)s * TLEN * ENCD + e;
    float sum = 0.0f;
#pragma unroll
    for (int t = 0; t < TLEN; t++) sum += p[t * ENCD];
    enc[s * ENCD + e] = sum / (float)__ldg(&lengths[s]);
}

// ---------------------------------------------------------------------------
// Parser: 4-CTA cluster, unit-partitioned Wt (125 rows / 100 KB per CTA).
// SPECULATIVE gate GEMV on warps 0-7 runs concurrently with the score warp
// (the TreeLSTM input [s1;s0] is decision-independent). One mbarrier/step;
// arrives parallelized across tid<4. No fences, no L1 flushes.
// ---------------------------------------------------------------------------
#define PRS_WT    0
#define PRS_WA    25000
#define PRS_BT    26200
#define PRS_BUF   26328
#define PRS_G     27528
#define PRS_MISS  27656
#define PRS_SC    27856
#define PRS_MBAR  27860
#define PRS_TOTAL 27864
#define PR_THREADS 320
#define PCLUSTER 4

__global__ __cluster_dims__(PCLUSTER, 1, 1) __launch_bounds__(PR_THREADS, 1) void parser4(
    const float* __restrict__ missing, const float* __restrict__ Wa,
    const float* __restrict__ ba, const float* __restrict__ Wt,
    const float* __restrict__ bt, float* __restrict__ out)
{
    extern __shared__ float sm[];
    float* sWt   = sm + PRS_WT;    // 125 rows x 200
    float* sWa   = sm + PRS_WA;    // 1200
    float* sBt   = sm + PRS_BT;    // 125
    float* sBuf  = sm + PRS_BUF;   // 6 x 200
    float* sG    = sm + PRS_G;     // 125
    float* sMiss = sm + PRS_MISS;  // 200
    float* sSc   = sm + PRS_SC;    // 2
    const int tid = threadIdx.x;
    const unsigned int rank = ctarank();
    const unsigned int mbarA = smem_u32(sm + PRS_MBAR);
    const unsigned int sBufA = smem_u32(sBuf);

    // own Wt rows: local row r (0..124): gate g=r/25, unit u=r%25
    //   global row = g*100 + rank*25 + u
    for (int i = tid; i < 125 * 200; i += PR_THREADS) {
        int r = i / 200, k = i - r * 200;
        int grow = (r / 25) * 100 + (int)rank * 25 + (r % 25);
        sWt[i] = __ldg(&Wt[grow * 200 + k]);
    }
    for (int i = tid; i < 1200; i += PR_THREADS) sWa[i] = __ldg(&Wa[i]);
    if (tid < 125) {
        int grow = (tid / 25) * 100 + (int)rank * 25 + (tid % 25);
        sBt[tid] = __ldg(&bt[grow]);
    }
    if (tid < 200) {
        float mv = __ldg(&missing[tid]);
        sMiss[tid] = mv;
        sBuf[0 * 200 + tid] = mv;                    // i1 = missing
        sBuf[1 * 200 + tid] = mv;                    // i0 = missing
        sBuf[2 * 200 + tid] = __ldg(&g_enc[tid]);    // ib = enc[0]
    }
    const float ba0 = __ldg(&ba[0]), ba1 = __ldg(&ba[1]);
    if (tid == 0) mbar_init(mbarA, PCLUSTER);
    __syncthreads();
    asm volatile("barrier.cluster.arrive.aligned;" ::: "memory");
    asm volatile("barrier.cluster.wait.aligned;"   ::: "memory");

    int i1 = 0, i0 = 1, ib = 2, ipre = 3, ibn = 4, isp = 5;
    int sp = 0, bp = 0;
    const int warp = tid >> 5;

    for (int step = 0; step < 2 * NSEQ - 1; step++) {
        // ==== PHASE A: all independent work in parallel ====
        // warps 0-7: SPECULATIVE TreeLSTM gate GEMV over own 125 rows
        if (tid < 250) {
            int r = tid >> 1, ph = tid & 1;
            const float4* wp4 = (const float4*)(sWt + r * 200 + ph * 100);
            const float4* xp  = (const float4*)(sBuf + (ph ? i0 : i1) * 200);
            float acc = 0.0f;
#pragma unroll
            for (int q = 0; q < 25; q++) {
                float4 w = wp4[q], x = xp[q];
                acc += w.x * x.x + w.y * x.y + w.z * x.z + w.w * x.w;
            }
            unsigned msk = __activemask();
            acc += __shfl_xor_sync(msk, acc, 1);
            if (!ph) sG[r] = acc + sBt[r];
        }
        // warp 8: score GEMV (replicated in every CTA)
        if (warp == 8) {
            int lane = tid - 256;
            const float* w0 = sWa;
            const float* w1 = sWa + 600;
            const float* f1p = sBuf + i1 * 200;
            const float* f0p = sBuf + i0 * 200;
            const float* fbp = sBuf + ib * 200;
            float a0 = 0.0f, a1 = 0.0f;
#pragma unroll
            for (int k = 0; k < 7; k++) {
                int kk = lane + 32 * k;
                if (kk < 200) { float f = f1p[kk]; a0 += w0[kk] * f;       a1 += w1[kk] * f; }
            }
#pragma unroll
            for (int k = 0; k < 7; k++) {
                int kk = lane + 32 * k;
                if (kk < 200) { float f = f0p[kk]; a0 += w0[200 + kk] * f; a1 += w1[200 + kk] * f; }
            }
#pragma unroll
            for (int k = 0; k < 7; k++) {
                int kk = lane + 32 * k;
                if (kk < 200) { float f = fbp[kk]; a0 += w0[400 + kk] * f; a1 += w1[400 + kk] * f; }
            }
#pragma unroll
            for (int o = 16; o > 0; o >>= 1) {
                a0 += __shfl_down_sync(0xffffffffu, a0, o);
                a1 += __shfl_down_sync(0xffffffffu, a1, o);
            }
            if (lane == 0) { sSc[0] = a0 + ba0; sSc[1] = a1 + ba1; }
        }
        // warp 9: prefetch stack[sp-3] -> ipre, enc[bp+1] -> ibn
        if (warp == 9) {
            int lane = tid - 288;
            float4* dpre = (float4*)(sBuf + ipre * 200);
            float4* dbn  = (float4*)(sBuf + ibn  * 200);
            const float4* mi4 = (const float4*)sMiss;
            for (int q = lane; q < 50; q += 32)
                dpre[q] = (sp >= 3) ? ldcg4(&g_stk[(sp - 3) * ENCD + 4 * q]) : mi4[q];
            int nbp = bp + 1;
            for (int q = lane; q < 50; q += 32)
                dbn[q] = (nbp < NSEQ) ? __ldg(((const float4*)(g_enc + nbp * ENCD)) + q)
                                      : mi4[q];
        }
        __syncthreads();

        // ==== PHASE B: decision + commit ====
        float m0 = (bp < NSEQ) ? sSc[0] : -1e30f;
        float m1 = (sp >= 2)   ? sSc[1] : -1e30f;
        bool is_shift = (m0 >= m1);   // argmax, first-index tie-break

        if (is_shift) {
            // push b: CTA writes its 50-float quarter [rank*50, rank*50+50)
            if (tid < 25) {
                const float2* src = (const float2*)(sBuf + ib * 200 + (int)rank * 50);
                stcg2(&g_stk[sp * ENCD + (int)rank * 50 + 2 * tid], src[tid]);
            }
        } else {
            if (tid < 25) {
                int u = tid;
                int j = (int)rank * 25 + u;
                float gi = sG[u],        gf1 = sG[25 + u], gf2 = sG[50 + u];
                float go = sG[75 + u],   gu  = sG[100 + u];
                float c1 = sBuf[i1 * 200 + 100 + j];
                float c2 = sBuf[i0 * 200 + 100 + j];
                float c = sigf(gf1) * c1 + sigf(gf2) * c2 + sigf(gi) * tanh_acc(gu);
                float h = sigf(go) * tanh_acc(c);
                sBuf[isp * 200 + j]       = h;
                sBuf[isp * 200 + 100 + j] = c;
                unsigned int ah = sBufA + (unsigned int)(isp * 200 + j) * 4u;
                unsigned int ac = sBufA + (unsigned int)(isp * 200 + 100 + j) * 4u;
#pragma unroll
                for (unsigned int rk = 0; rk < PCLUSTER; rk++) {
                    if (rk != rank) { st_remote_f32(ah, rk, h); st_remote_f32(ac, rk, c); }
                }
                stcg(&g_stk[(sp - 2) * ENCD + j], h);
                stcg(&g_stk[(sp - 2) * ENCD + 100 + j], c);
            }
        }
        __syncthreads();
        if (tid < PCLUSTER) mbar_arrive_rank(mbarA, (unsigned int)tid);
        mbar_wait_cl(mbarA, (unsigned int)(step & 1));

        // ---- rotate ring indices (uniform across CTAs) ----
        if (is_shift) {
            int t = i1; i1 = i0; i0 = ib; ib = ibn; ibn = t;
            sp += 1; bp += 1;
        } else {
            int n1 = ipre, n0 = isp;
            ipre = i1; isp = i0;
            i1 = n1; i0 = n0;
            sp -= 1;
        }
    }

    if (rank == 0 && tid < 50) {
        float4 v = ldcg4(&g_stk[4 * tid]);
        ((float4*)out)[tid] = v;
    }
}

// ---------------------------------------------------------------------------
extern "C" void kernel_launch(void* const* d_in, const int* in_sizes, int n_in,
                              void* d_out, int out_size)
{
    const int*   tokens  = (const int*)d_in[0];
    const int*   lengths = (const int*)d_in[1];
    const float* emb     = (const float*)d_in[2];
    const float* Wih0    = (const float*)d_in[3];
    const float* Whh0    = (const float*)d_in[4];
    const float* b0      = (const float*)d_in[5];
    const float* Wih12   = (const float*)d_in[6];
    const float* Whh12   = (const float*)d_in[7];
    const float* b12     = (const float*)d_in[8];
    const float* missing = (const float*)d_in[9];
    const float* Wa      = (const float*)d_in[10];
    const float* ba      = (const float*)d_in[11];
    const float* Wt      = (const float*)d_in[12];
    const float* bt      = (const float*)d_in[13];
    float* out = (float*)d_out;

    float *P, *Ya, *Yb, *enc;
    cudaGetSymbolAddress((void**)&P,  g_P);
    cudaGetSymbolAddress((void**)&Ya, g_Ya);
    cudaGetSymbolAddress((void**)&Yb, g_Yb);
    cudaGetSymbolAddress((void**)&enc, g_enc);

    const int lstmSmem = (40000 + 400 + 400 + 1600) * 4;   // 169600
    const int parsSmem = PRS_TOTAL * 4;                    // 111456
    cudaFuncSetAttribute(lstm_rec, cudaFuncAttributeMaxDynamicSharedMemorySize, lstmSmem);
    cudaFuncSetAttribute(parser4, cudaFuncAttributeMaxDynamicSharedMemorySize, parsSmem);

    dim3 gg(128, 10), rg(64, 2);

    // layer 0
    proj_gemm<<<gg, 256>>>(emb, tokens, Wih0, b0, P, 300);
    lstm_rec<<<rg, 400, lstmSmem>>>(P, Whh0, lengths, Ya);
    // layer 1
    proj_gemm<<<gg, 256>>>(Ya, nullptr, Wih12, b12, P, 200);
    lstm_rec<<<rg, 400, lstmSmem>>>(P, Whh12, lengths, Yb);
    // layer 2
    proj_gemm<<<gg, 256>>>(Yb, nullptr, Wih12 + 160000, b12 + 800, P, 200);
    lstm_rec<<<rg, 400, lstmSmem>>>(P, Whh12 + 80000, lengths, Ya);
    // pool + parse
    meanpool<<<NSEQ, 200>>>(Ya, lengths, enc);
    parser4<<<PCLUSTER, PR_THREADS, parsSmem>>>(missing, Wa, ba, Wt, bt, out);
}